// round 4
// baseline (speedup 1.0000x reference)
#include <cuda_runtime.h>
#include <cstdint>

#define B_ 4096
#define T_ 120
#define I_ 64
#define H_ 128
#define G_ 384   // 3*H

// Scratch for input-side gate pre-activations, layout [t][B][G],
// gate-interleaved columns: col' = j*3 + gate, gate in {r=0,z=1,n=2}
__device__ float g_xg[(size_t)B_ * T_ * G_];

// ---- packed f32x2 helpers ----
#define FMA2(d, a, b) \
    asm("fma.rn.f32x2 %0, %1, %2, %0;" : "+l"(d) : "l"(a), "l"(b))

#define UNPACK2(lo, hi, p) do {                                     \
    unsigned int _l, _h;                                            \
    asm("mov.b64 {%0, %1}, %2;" : "=r"(_l), "=r"(_h) : "l"(p));     \
    (lo) = __uint_as_float(_l); (hi) = __uint_as_float(_h);         \
} while (0)

#define TANHA(y, x) asm("tanh.approx.f32 %0, %1;" : "=f"(y) : "f"(x))

__device__ __forceinline__ float sigmoid_mufu(float x) {
    float th; TANHA(th, 0.5f * x);
    return fmaf(0.5f, th, 0.5f);
}
__device__ __forceinline__ float tanh_mufu(float x) {
    float th; TANHA(th, x);
    return th;
}

// =====================================================================
// Kernel 1: x_gates = x @ W_ih^T + b_ih  -> g_xg[t][B][G]
// 512 threads, 128 rows x 384 cols (2 col halves), tile 4 rows x 12 cols.
// x stored DUPLICATED in smem -> zero packing in inner loop.
// =====================================================================
#define K1_SMEM ((64 * G_ + 64 * 256 + G_) * 4)   // 165376 B

__global__ __launch_bounds__(512, 1) void k1_xgates(
    const float* __restrict__ x,
    const float* __restrict__ Wih,
    const float* __restrict__ bih)
{
    extern __shared__ float sm[];
    float* Wt  = sm;               // [64][384]  WihT[i][col']
    float* xTd = Wt + 64 * G_;     // [64][256]  x dup: [i][2r],[i][2r+1]
    float* bI  = xTd + 64 * 256;   // [384] reordered bias

    const int tid = threadIdx.x;
    const size_t r0 = (size_t)blockIdx.x * 128;

    for (int idx = tid; idx < G_ * I_; idx += 512) {
        int g = idx >> 6, i = idx & 63;
        Wt[i * G_ + ((g & 127) * 3 + (g >> 7))] = Wih[idx];
    }
    for (int g = tid; g < G_; g += 512)
        bI[(g & 127) * 3 + (g >> 7)] = bih[g];
    for (int idx = tid; idx < 128 * I_; idx += 512) {
        int r = idx >> 6, i = idx & 63;
        float v = x[(r0 + r) * I_ + i];
        *(float2*)(xTd + i * 256 + 2 * r) = make_float2(v, v);
    }
    __syncthreads();

    const int lane = tid & 31, warp = tid >> 5;
    const int mblk = (warp & 3) * 8 + (lane & 7);     // 0..31 -> 4 rows each
    const int jblk = (warp >> 2) * 4 + (lane >> 3);   // 0..15 -> 12 cols each
    const int m0 = mblk * 4;

    for (int half = 0; half < 2; half++) {
        const int c0 = half * 192 + jblk * 12;

        unsigned long long acc[4][6];
        #pragma unroll
        for (int c = 0; c < 6; c++) {
            unsigned long long bp = *(const unsigned long long*)(bI + c0 + 2 * c);
            #pragma unroll
            for (int p = 0; p < 4; p++) acc[p][c] = bp;
        }

        #pragma unroll 4
        for (int k = 0; k < 64; k++) {
            const float* xrow = xTd + k * 256 + 8 * mblk;
            ulonglong2 xa = *(const ulonglong2*)(xrow);      // (x0,x0),(x1,x1)
            ulonglong2 xb = *(const ulonglong2*)(xrow + 4);  // (x2,x2),(x3,x3)
            unsigned long long hp[4] = {xa.x, xa.y, xb.x, xb.y};
            const float* wrow = Wt + k * G_ + c0;
            ulonglong2 wa = *(const ulonglong2*)(wrow);
            ulonglong2 wb = *(const ulonglong2*)(wrow + 4);
            ulonglong2 wc = *(const ulonglong2*)(wrow + 8);
            unsigned long long wp[6] = {wa.x, wa.y, wb.x, wb.y, wc.x, wc.y};
            #pragma unroll
            for (int p = 0; p < 4; p++) {
                #pragma unroll
                for (int c = 0; c < 6; c++) FMA2(acc[p][c], hp[p], wp[c]);
            }
        }

        #pragma unroll
        for (int p = 0; p < 4; p++) {
            float v[12];
            #pragma unroll
            for (int c = 0; c < 6; c++) UNPACK2(v[2 * c], v[2 * c + 1], acc[p][c]);
            unsigned int r = (unsigned int)(r0 + m0 + p);
            unsigned int b = r / T_, t = r % T_;
            float* dst = g_xg + ((size_t)t * B_ + b) * G_ + c0;
            *(float4*)(dst)     = make_float4(v[0], v[1], v[2],  v[3]);
            *(float4*)(dst + 4) = make_float4(v[4], v[5], v[6],  v[7]);
            *(float4*)(dst + 8) = make_float4(v[8], v[9], v[10], v[11]);
        }
    }
}

// =====================================================================
// Kernel 2: recurrence. 128 CTAs x 32 batch rows, 512 threads.
// Tile: 2 rows x 12 cols. h stored DUPLICATED in smem: zero packing.
// =====================================================================
#define K2_SMEM ((128 * G_ + 128 * 64 + G_) * 4)   // 230912 B

__global__ __launch_bounds__(512, 1) void k2_recur(
    const float* __restrict__ Whh,
    const float* __restrict__ bhh,
    float* __restrict__ out,      // [B, T, H]
    float* __restrict__ hT_out)   // [B, H]
{
    extern __shared__ float sm[];
    float* Wt   = sm;                  // [128][384]  WhhT[k][col']
    float* hTmd = Wt + 128 * G_;       // [128][64]   h dup: [k][2m],[k][2m+1]
    float* bI   = hTmd + 128 * 64;     // [384] reordered bias

    const int tid = threadIdx.x;
    const size_t b0 = (size_t)blockIdx.x * 32;

    for (int idx = tid; idx < G_ * H_; idx += 512) {
        int g = idx >> 7, k = idx & 127;
        Wt[k * G_ + ((g & 127) * 3 + (g >> 7))] = Whh[idx];
    }
    for (int g = tid; g < G_; g += 512)
        bI[(g & 127) * 3 + (g >> 7)] = bhh[g];
    for (int idx = tid; idx < 128 * 64; idx += 512) hTmd[idx] = 0.0f;
    __syncthreads();

    const int mblk = tid & 15;    // 16 blocks of 2 rows
    const int jblk = tid >> 4;    // 32 blocks of 12 cols
    const int c0 = jblk * 12;
    const int j0 = jblk * 4;
    const size_t row0 = b0 + 2 * mblk;   // first of the 2 rows

    unsigned long long bias[6];
    #pragma unroll
    for (int c = 0; c < 6; c++)
        bias[c] = *(const unsigned long long*)(bI + c0 + 2 * c);

    float hprev[2][4];
    #pragma unroll
    for (int mi = 0; mi < 2; mi++)
        #pragma unroll
        for (int ji = 0; ji < 4; ji++) hprev[mi][ji] = 0.0f;

    for (int t = 0; t < T_; t++) {
        // Prefetch input-side gate values (contiguous block per CTA-step)
        float xf[2][12];
        #pragma unroll
        for (int mi = 0; mi < 2; mi++) {
            const float* p = g_xg + ((size_t)t * B_ + row0 + mi) * G_ + c0;
            float4 a = *(const float4*)(p);
            float4 b = *(const float4*)(p + 4);
            float4 c = *(const float4*)(p + 8);
            xf[mi][0] = a.x; xf[mi][1]  = a.y; xf[mi][2]  = a.z; xf[mi][3]  = a.w;
            xf[mi][4] = b.x; xf[mi][5]  = b.y; xf[mi][6]  = b.z; xf[mi][7]  = b.w;
            xf[mi][8] = c.x; xf[mi][9]  = c.y; xf[mi][10] = c.z; xf[mi][11] = c.w;
        }

        // hg = h @ W_hh^T + b_hh; acc[row][colpair]
        unsigned long long acc[2][6];
        #pragma unroll
        for (int r = 0; r < 2; r++)
            #pragma unroll
            for (int c = 0; c < 6; c++) acc[r][c] = bias[c];

        #pragma unroll 4
        for (int k = 0; k < 128; k++) {
            // (h0,h0,h1,h1) -> two ready f32x2 multiplicands, zero packing
            ulonglong2 hv = *(const ulonglong2*)(hTmd + k * 64 + 4 * mblk);
            const float* wrow = Wt + k * G_ + c0;
            ulonglong2 wa = *(const ulonglong2*)(wrow);
            ulonglong2 wb = *(const ulonglong2*)(wrow + 4);
            ulonglong2 wc = *(const ulonglong2*)(wrow + 8);
            unsigned long long wp[6] = {wa.x, wa.y, wb.x, wb.y, wc.x, wc.y};
            #pragma unroll
            for (int c = 0; c < 6; c++) {
                FMA2(acc[0][c], hv.x, wp[c]);
                FMA2(acc[1][c], hv.y, wp[c]);
            }
        }
        __syncthreads();   // all hTmd reads done before rewrites

        float hg[2][12];
        #pragma unroll
        for (int r = 0; r < 2; r++)
            #pragma unroll
            for (int c = 0; c < 6; c++)
                UNPACK2(hg[r][2 * c], hg[r][2 * c + 1], acc[r][c]);

        #pragma unroll
        for (int mi = 0; mi < 2; mi++) {
            float o[4];
            #pragma unroll
            for (int ji = 0; ji < 4; ji++) {
                float r = sigmoid_mufu(xf[mi][ji * 3 + 0] + hg[mi][ji * 3 + 0]);
                float z = sigmoid_mufu(xf[mi][ji * 3 + 1] + hg[mi][ji * 3 + 1]);
                float n = tanh_mufu(xf[mi][ji * 3 + 2] + r * hg[mi][ji * 3 + 2]);
                float h = n + z * (hprev[mi][ji] - n);
                hprev[mi][ji] = h;
                o[ji] = h;
            }
            *(float4*)(out + ((row0 + mi) * (size_t)T_ + t) * H_ + j0) =
                make_float4(o[0], o[1], o[2], o[3]);
        }

        // Publish duplicated h pairs for next step
        #pragma unroll
        for (int ji = 0; ji < 4; ji++)
            *(float4*)(hTmd + (j0 + ji) * 64 + 4 * mblk) =
                make_float4(hprev[0][ji], hprev[0][ji], hprev[1][ji], hprev[1][ji]);
        __syncthreads();
    }

    #pragma unroll
    for (int mi = 0; mi < 2; mi++)
        *(float4*)(hT_out + (row0 + mi) * H_ + j0) =
            make_float4(hprev[mi][0], hprev[mi][1], hprev[mi][2], hprev[mi][3]);
}

extern "C" void kernel_launch(void* const* d_in, const int* in_sizes, int n_in,
                              void* d_out, int out_size)
{
    const float* x   = (const float*)d_in[0];
    const float* Wih = (const float*)d_in[1];
    const float* Whh = (const float*)d_in[2];
    const float* bih = (const float*)d_in[3];
    const float* bhh = (const float*)d_in[4];

    float* out = (float*)d_out;                       // [B, T, H]
    float* hT  = out + (size_t)B_ * T_ * H_;          // [B, H]

    cudaFuncSetAttribute(k1_xgates, cudaFuncAttributeMaxDynamicSharedMemorySize, K1_SMEM);
    cudaFuncSetAttribute(k2_recur,  cudaFuncAttributeMaxDynamicSharedMemorySize, K2_SMEM);

    k1_xgates<<<(B_ * T_) / 128, 512, K1_SMEM>>>(x, Wih, bih);
    k2_recur<<<B_ / 32, 512, K2_SMEM>>>(Whh, bhh, out, hT);
}